// round 13
// baseline (speedup 1.0000x reference)
#include <cuda_runtime.h>
#include <math.h>
#include <float.h>

#define A_N 33600
#define G_N 256
#define C_N 80
#define TOPK 10
#define NT   512
#define GPB  2
#define CAP  1792        // max inside anchors/GT; max box 208x208 -> mean ~890, +30 sigma
#define PREP_NT 256
#define PREP_BLOCKS 2100 // 2100*256 threads; warp w handles score rows 2w, 2w+1
#define SENT 0xFFFFFFFFFFFFFFFFULL

// Scratch (allocation-free: __device__ globals)
__device__ float g_total_neg[A_N];
__device__ int   g_assigned[A_N];

// monotone float -> uint mapping, packed with index: lexicographic (cost asc, idx asc)
__device__ __forceinline__ unsigned long long packKey(float v, unsigned idx) {
    unsigned u = __float_as_uint(v);
    u = (u & 0x80000000u) ? ~u : (u | 0x80000000u);
    return (((unsigned long long)u) << 32) | (unsigned long long)idx;
}

// softplus difference with the reference's rounding sequence
__device__ __forceinline__ float sp_diff(float s) {
    float l = log1pf(expf(-fabsf(s)));
    return (fmaxf(-s, 0.0f) + l) - (fmaxf(s, 0.0f) + l);
}

// fast softplus of 4 values: max(x,0) + log(1 + exp(-|x|)), arg of log in (1,2]
__device__ __forceinline__ float sp4(float4 v) {
    float s;
    s  = fmaxf(v.x, 0.0f) + __logf(1.0f + __expf(-fabsf(v.x)));
    s += fmaxf(v.y, 0.0f) + __logf(1.0f + __expf(-fabsf(v.y)));
    s += fmaxf(v.z, 0.0f) + __logf(1.0f + __expf(-fabsf(v.z)));
    s += fmaxf(v.w, 0.0f) + __logf(1.0f + __expf(-fabsf(v.w)));
    return s;
}

// ---- kernel 1: prep = total_neg (2 rows/warp, float4) + init + zero scores ----
__global__ __launch_bounds__(PREP_NT) void prep_kernel(
    const float* __restrict__ scores, float* __restrict__ out)
{
    const int gid = blockIdx.x * PREP_NT + threadIdx.x;

    if (gid < A_N) g_assigned[gid] = -1;

    const int n4 = (A_N * (C_N + 1)) / 4;   // 680400 float4s in the scores region
    float4* zp = (float4*)(out + (size_t)5 * A_N);
    for (int i = gid; i < n4; i += PREP_BLOCKS * PREP_NT)
        zp[i] = make_float4(0.f, 0.f, 0.f, 0.f);

    // warp w covers rows r0=2w, r1=2w+1: 40 float4s = 640 contiguous bytes
    const int w = gid >> 5, lane = gid & 31;
    const float4* s4 = (const float4*)scores;
    const size_t B = (size_t)w * 40;

    float4 v = __ldg(s4 + B + lane);            // idx 0..31 (row0: <20, row1: >=20)
    float t = sp4(v);
    float s0 = (lane < 20) ? t : 0.0f;
    float s1 = (lane < 20) ? 0.0f : t;
    if (lane < 8) s1 += sp4(__ldg(s4 + B + 32 + lane));   // idx 32..39 (row1)

#pragma unroll
    for (int o = 16; o; o >>= 1) {
        s0 += __shfl_xor_sync(0xffffffffu, s0, o);
        s1 += __shfl_xor_sync(0xffffffffu, s1, o);
    }
    if (lane == 0)
        *(float2*)(g_total_neg + 2 * w) = make_float2(s0, s1);
}

// ---- kernel 2: 2-GT compact sweep -> split-half dense cost -> dual warp top-k ----
__global__ __launch_bounds__(NT) void topk_kernel(
    const float* __restrict__ pred_scores,
    const float* __restrict__ pred_bboxes,
    const float* __restrict__ anchor_points,
    const int*   __restrict__ gt_labels,
    const float* __restrict__ gt_bboxes)
{
    const int g0  = blockIdx.x * GPB;
    const int tid = threadIdx.x;
    const int lane = tid & 31, wid = tid >> 5;

    __shared__ int s_list[GPB][CAP];
    __shared__ unsigned long long s_keys[GPB][CAP];
    __shared__ unsigned long long swmin[NT / 32];
    __shared__ float4 s_gt[GPB];
    __shared__ int s_lab[GPB];
    __shared__ int s_n[GPB];
    __shared__ int s_cnt[GPB];

    if (tid < GPB) {
        s_n[tid] = 0; s_cnt[tid] = 0;
        s_gt[tid]  = ((const float4*)gt_bboxes)[g0 + tid];
        s_lab[tid] = gt_labels[g0 + tid];
    }
    __syncthreads();

    const float4 b0 = s_gt[0], b1 = s_gt[1];
    const float2* ap2 = (const float2*)anchor_points;
    const float4* pb4 = (const float4*)pred_bboxes;

    // ---- phase 1: cheap inside scan for both GTs (inside == in_gt) ----
    for (int a = tid; a < A_N; a += NT) {
        float2 p = __ldg(ap2 + a);
        bool i0 = (p.x >= b0.x) & (p.x <= b0.z) & (p.y >= b0.y) & (p.y <= b0.w);
        bool i1 = (p.x >= b1.x) & (p.x <= b1.z) & (p.y >= b1.y) & (p.y <= b1.w);
        if (i0) { int s = atomicAdd(&s_n[0], 1); if (s < CAP) s_list[0][s] = a; }
        if (i1) { int s = atomicAdd(&s_n[1], 1); if (s < CAP) s_list[1][s] = a; }
    }
    __syncthreads();

    // ---- rare fallback: GT with zero inside anchors -> global argmin, dyn_k=1 ----
#pragma unroll
    for (int gi = 0; gi < GPB; gi++) {
        if (s_n[gi] == 0) {   // uniform (smem, post-sync)
            const float4 gb = s_gt[gi];
            const int L = s_lab[gi];
            const float area_g = (gb.z - gb.x) * (gb.w - gb.y);
            unsigned long long best = SENT;
            for (int a = tid; a < A_N; a += NT) {
                float4 pb = __ldg(pb4 + a);
                float w  = fmaxf(fminf(pb.z, gb.z) - fmaxf(pb.x, gb.x), 0.0f);
                float h  = fmaxf(fminf(pb.w, gb.w) - fmaxf(pb.y, gb.y), 0.0f);
                float ov = w * h;
                float area_p = (pb.z - pb.x) * (pb.w - pb.y);
                float iou  = ov / (area_p + area_g - ov + 1e-6f);
                float iouc = -logf(fmaxf(iou, 1e-7f));
                float s    = __ldg(pred_scores + (size_t)a * C_N + L);
                float cls  = g_total_neg[a] + sp_diff(s);
                float cost = __fadd_rn(__fadd_rn(cls, __fmul_rn(3.0f, iouc)), 1e10f);
                unsigned long long k = packKey(cost, (unsigned)a);
                if (k < best) best = k;
            }
            for (int o = 16; o; o >>= 1) {
                unsigned long long oth = __shfl_down_sync(0xffffffffu, best, o);
                best = (oth < best) ? oth : best;
            }
            if (lane == 0) swmin[wid] = best;
            __syncthreads();
            if (tid == 0) {
                unsigned long long w = swmin[0];
                for (int i = 1; i < NT / 32; i++) if (swmin[i] < w) w = swmin[i];
                atomicMax(&g_assigned[(int)(w & 0xffffffffu)], g0 + gi);
            }
            __syncthreads();
        }
    }

    // ---- phase 2: half-block per GT, dense cost over compacted list ----
    const int half = wid >> 3;       // warps 0-7 -> GT0, warps 8-15 -> GT1
    const int htid = tid & 255;
    {
        const float4 gb = s_gt[half];
        const int L = s_lab[half];
        const float area_g = (gb.z - gb.x) * (gb.w - gb.y);
        const int n = min(s_n[half], CAP);
        for (int i = htid; i < n; i += 256) {
            int a = s_list[half][i];
            float4 pb = __ldg(pb4 + a);
            float w  = fmaxf(fminf(pb.z, gb.z) - fmaxf(pb.x, gb.x), 0.0f);
            float h  = fmaxf(fminf(pb.w, gb.w) - fmaxf(pb.y, gb.y), 0.0f);
            float ov = w * h;
            if (ov > 0.0f) atomicAdd(&s_cnt[half], 1);
            float area_p = (pb.z - pb.x) * (pb.w - pb.y);
            float iou  = ov / (area_p + area_g - ov + 1e-6f);
            float iouc = -logf(fmaxf(iou, 1e-7f));
            float s    = __ldg(pred_scores + (size_t)a * C_N + L);
            float cls  = g_total_neg[a] + sp_diff(s);
            float cost = __fadd_rn(cls, __fmul_rn(3.0f, iouc));
            s_keys[half][i] = packKey(cost, (unsigned)a);
        }
    }
    __syncthreads();

    // ---- phase 3: warp 0 of each half -> exact top-dyn_k selection + scatter ----
    if ((wid & 7) == 0) {
        const int gi = half;
        const int n = min(s_n[gi], CAP);
        if (n > 0) {
            int cnt = s_cnt[gi];
            int k = (cnt < 1) ? 1 : ((cnt > TOPK) ? TOPK : cnt);
            // dyn_k <= cnt <= n, and every inside cost < every outside cost,
            // so the global top-dyn_k are exactly among these candidates.
            unsigned long long loc[TOPK];
#pragma unroll
            for (int j = 0; j < TOPK; j++) loc[j] = SENT;
            for (int i = lane; i < n; i += 32) {
                unsigned long long v = s_keys[gi][i];
                if (v < loc[TOPK - 1]) {
                    loc[TOPK - 1] = v;
#pragma unroll
                    for (int j = TOPK - 1; j > 0; j--) {
                        bool sw = loc[j] < loc[j - 1];
                        unsigned long long lo = sw ? loc[j] : loc[j - 1];
                        unsigned long long hi = sw ? loc[j - 1] : loc[j];
                        loc[j - 1] = lo; loc[j] = hi;
                    }
                }
            }
            int p = 0;
            for (int r = 0; r < k; r++) {
                unsigned long long cand = (p < TOPK) ? loc[p] : SENT;
                unsigned long long m = cand;
#pragma unroll
                for (int o = 16; o; o >>= 1) {
                    unsigned long long oth = __shfl_xor_sync(0xffffffffu, m, o);
                    m = (oth < m) ? oth : m;
                }
                if (lane == 0) atomicMax(&g_assigned[(int)(m & 0xffffffffu)], g0 + gi);
                if (cand == m) p++;
            }
        }
    }
}

// ---- kernel 3: labels + bboxes + one-hot scatter (scores pre-zeroed) ----
__global__ void finalize_kernel(const float* __restrict__ pred_bboxes,
                                const int*   __restrict__ gt_labels,
                                const float* __restrict__ gt_bboxes,
                                float* __restrict__ out)
{
    int a = blockIdx.x * blockDim.x + threadIdx.x;
    if (a >= A_N) return;

    int  g    = g_assigned[a];
    bool pos  = (g >= 0);
    int  safe = pos ? g : 0;
    int  label = pos ? gt_labels[safe] : C_N;

    float4 gbx = ((const float4*)gt_bboxes)[safe];

    out[a] = (float)label;

    float4* ob = (float4*)(out + A_N);
    ob[a] = pos ? gbx : make_float4(0.f, 0.f, 0.f, 0.f);

    if (pos) {
        float4 pb = ((const float4*)pred_bboxes)[a];
        float w = fmaxf(fminf(pb.z, gbx.z) - fmaxf(pb.x, gbx.x), 0.0f);
        float h = fmaxf(fminf(pb.w, gbx.w) - fmaxf(pb.y, gbx.y), 0.0f);
        float ov = w * h;
        float area_p = (pb.z - pb.x) * (pb.w - pb.y);
        float area_g = (gbx.z - gbx.x) * (gbx.w - gbx.y);
        float iou = ov / (area_p + area_g - ov + 1e-6f);
        out[(size_t)5 * A_N + (size_t)a * (C_N + 1) + label] = iou;
    }
}

extern "C" void kernel_launch(void* const* d_in, const int* in_sizes, int n_in,
                              void* d_out, int out_size) {
    const float* pred_scores   = (const float*)d_in[0];
    const float* pred_bboxes   = (const float*)d_in[1];
    const float* anchor_points = (const float*)d_in[2];
    const int*   gt_labels     = (const int*)  d_in[3];
    const float* gt_bboxes     = (const float*)d_in[4];
    float* out = (float*)d_out;

    prep_kernel<<<PREP_BLOCKS, PREP_NT>>>(pred_scores, out);
    topk_kernel<<<G_N / GPB, NT>>>(pred_scores, pred_bboxes, anchor_points,
                                   gt_labels, gt_bboxes);
    finalize_kernel<<<(A_N + 255) / 256, 256>>>(pred_bboxes, gt_labels, gt_bboxes, out);
}

// round 14
// speedup vs baseline: 1.2412x; 1.2412x over previous
#include <cuda_runtime.h>
#include <math.h>
#include <float.h>

#define A_N 33600
#define G_N 256
#define C_N 80
#define TOPK 10
#define NT   512
#define CAP  2048        // max inside anchors/GT; 208x208 box -> mean ~887, sigma ~29
#define PREP_NT 256
#define PREP_BLOCKS 2100 // warp w handles score rows 2w, 2w+1
#define SENT 0xFFFFFFFFFFFFFFFFULL

// Scratch (allocation-free: __device__ globals)
__device__ float g_total_neg[A_N];
__device__ int   g_assigned[A_N];

// monotone float -> uint mapping, packed with index: lexicographic (cost asc, idx asc)
__device__ __forceinline__ unsigned long long packKey(float v, unsigned idx) {
    unsigned u = __float_as_uint(v);
    u = (u & 0x80000000u) ? ~u : (u | 0x80000000u);
    return (((unsigned long long)u) << 32) | (unsigned long long)idx;
}

// softplus difference with the reference's rounding sequence
__device__ __forceinline__ float sp_diff(float s) {
    float l = log1pf(expf(-fabsf(s)));
    return (fmaxf(-s, 0.0f) + l) - (fmaxf(s, 0.0f) + l);
}

// fast softplus of 4 values: max(x,0) + log(1 + exp(-|x|)), arg of log in (1,2]
__device__ __forceinline__ float sp4(float4 v) {
    float s;
    s  = fmaxf(v.x, 0.0f) + __logf(1.0f + __expf(-fabsf(v.x)));
    s += fmaxf(v.y, 0.0f) + __logf(1.0f + __expf(-fabsf(v.y)));
    s += fmaxf(v.z, 0.0f) + __logf(1.0f + __expf(-fabsf(v.z)));
    s += fmaxf(v.w, 0.0f) + __logf(1.0f + __expf(-fabsf(v.w)));
    return s;
}

// ---- kernel 1: prep = total_neg (2 rows/warp, float4) + init + zero scores ----
__global__ __launch_bounds__(PREP_NT) void prep_kernel(
    const float* __restrict__ scores, float* __restrict__ out)
{
    const int gid = blockIdx.x * PREP_NT + threadIdx.x;

    if (gid < A_N) g_assigned[gid] = -1;

    const int n4 = (A_N * (C_N + 1)) / 4;   // 680400 float4s in the scores region
    float4* zp = (float4*)(out + (size_t)5 * A_N);
    for (int i = gid; i < n4; i += PREP_BLOCKS * PREP_NT)
        zp[i] = make_float4(0.f, 0.f, 0.f, 0.f);

    // warp w covers rows r0=2w, r1=2w+1: 40 float4s = 640 contiguous bytes
    const int w = gid >> 5, lane = gid & 31;
    const float4* s4 = (const float4*)scores;
    const size_t B = (size_t)w * 40;

    float4 v = __ldg(s4 + B + lane);            // idx 0..31 (row0: <20, row1: >=20)
    float t = sp4(v);
    float s0 = (lane < 20) ? t : 0.0f;
    float s1 = (lane < 20) ? 0.0f : t;
    if (lane < 8) s1 += sp4(__ldg(s4 + B + 32 + lane));   // idx 32..39 (row1)

#pragma unroll
    for (int o = 16; o; o >>= 1) {
        s0 += __shfl_xor_sync(0xffffffffu, s0, o);
        s1 += __shfl_xor_sync(0xffffffffu, s1, o);
    }
    if (lane == 0)
        *(float2*)(g_total_neg + 2 * w) = make_float2(s0, s1);
}

// ---- kernel 2: per-GT compact scan -> dense cost -> warp top-k -> scatter ----
__global__ __launch_bounds__(NT) void topk_kernel(
    const float* __restrict__ pred_scores,
    const float* __restrict__ pred_bboxes,
    const float* __restrict__ anchor_points,
    const int*   __restrict__ gt_labels,
    const float* __restrict__ gt_bboxes)
{
    const int g   = blockIdx.x;
    const int tid = threadIdx.x;
    const int lane = tid & 31, wid = tid >> 5;

    const float4 gb = ((const float4*)gt_bboxes)[g];
    const float gx1 = gb.x, gy1 = gb.y, gx2 = gb.z, gy2 = gb.w;
    const int   L   = gt_labels[g];
    const float area_g = (gx2 - gx1) * (gy2 - gy1);

    const float4* ap4 = (const float4*)anchor_points;   // 2 anchors per float4
    const float4* pb4 = (const float4*)pred_bboxes;

    __shared__ int s_list[CAP];
    __shared__ unsigned long long s_keys[CAP];
    __shared__ unsigned long long swmin[NT / 32];
    __shared__ int s_n;
    __shared__ int s_cnt;

    if (tid == 0) { s_n = 0; s_cnt = 0; }
    __syncthreads();

    // ---- phase 1: cheap inside scan, 2 anchors per load (inside == in_gt) ----
    for (int i = tid; i < A_N / 2; i += NT) {
        float4 q = __ldg(ap4 + i);
        bool i0 = (q.x >= gx1) & (q.x <= gx2) & (q.y >= gy1) & (q.y <= gy2);
        bool i1 = (q.z >= gx1) & (q.z <= gx2) & (q.w >= gy1) & (q.w <= gy2);
        if (i0) { int s = atomicAdd(&s_n, 1); if (s < CAP) s_list[s] = 2 * i; }
        if (i1) { int s = atomicAdd(&s_n, 1); if (s < CAP) s_list[s] = 2 * i + 1; }
    }
    __syncthreads();
    const int n = min(s_n, CAP);

    if (n > 0) {
        // ---- phase 2: dense cost over compacted candidates (mask = 0 inside) ----
        int cnt = 0;
        for (int i = tid; i < n; i += NT) {
            int a = s_list[i];
            float4 pb = __ldg(pb4 + a);
            float w  = fmaxf(fminf(pb.z, gx2) - fmaxf(pb.x, gx1), 0.0f);
            float h  = fmaxf(fminf(pb.w, gy2) - fmaxf(pb.y, gy1), 0.0f);
            float ov = w * h;
            cnt += (ov > 0.0f);
            float area_p = (pb.z - pb.x) * (pb.w - pb.y);
            float iou  = ov / (area_p + area_g - ov + 1e-6f);
            float iouc = -logf(fmaxf(iou, 1e-7f));
            float s    = __ldg(pred_scores + (size_t)a * C_N + L);
            float cls  = g_total_neg[a] + sp_diff(s);
            float cost = __fadd_rn(cls, __fmul_rn(3.0f, iouc));
            s_keys[i] = packKey(cost, (unsigned)a);
        }
        for (int o = 16; o; o >>= 1) cnt += __shfl_down_sync(0xffffffffu, cnt, o);
        if (lane == 0 && cnt > 0) atomicAdd(&s_cnt, cnt);
        __syncthreads();

        // ---- phase 3: single-warp exact top-dyn_k selection + scatter ----
        if (wid == 0) {
            int c = s_cnt;
            int k = (c < 1) ? 1 : ((c > TOPK) ? TOPK : c);
            // dyn_k <= cnt <= n, and every inside cost < every outside cost,
            // so the global top-dyn_k are exactly among these candidates.
            unsigned long long loc[TOPK];
#pragma unroll
            for (int j = 0; j < TOPK; j++) loc[j] = SENT;
            for (int i = lane; i < n; i += 32) {
                unsigned long long v = s_keys[i];
                if (v < loc[TOPK - 1]) {
                    loc[TOPK - 1] = v;
#pragma unroll
                    for (int j = TOPK - 1; j > 0; j--) {
                        bool sw = loc[j] < loc[j - 1];
                        unsigned long long lo = sw ? loc[j] : loc[j - 1];
                        unsigned long long hi = sw ? loc[j - 1] : loc[j];
                        loc[j - 1] = lo; loc[j] = hi;
                    }
                }
            }
            int p = 0;
            for (int r = 0; r < k; r++) {
                unsigned long long cand = (p < TOPK) ? loc[p] : SENT;
                unsigned long long m = cand;
#pragma unroll
                for (int o = 16; o; o >>= 1) {
                    unsigned long long oth = __shfl_xor_sync(0xffffffffu, m, o);
                    m = (oth < m) ? oth : m;
                }
                if (lane == 0) atomicMax(&g_assigned[(int)(m & 0xffffffffu)], g);
                if (cand == m) p++;
            }
        }
    } else {
        // ---- zero inside anchors: dyn_k = 1, global argmin (all outside) ----
        unsigned long long best = SENT;
        for (int a = tid; a < A_N; a += NT) {
            float4 pb = __ldg(pb4 + a);
            float w  = fmaxf(fminf(pb.z, gx2) - fmaxf(pb.x, gx1), 0.0f);
            float h  = fmaxf(fminf(pb.w, gy2) - fmaxf(pb.y, gy1), 0.0f);
            float ov = w * h;
            float area_p = (pb.z - pb.x) * (pb.w - pb.y);
            float iou  = ov / (area_p + area_g - ov + 1e-6f);
            float iouc = -logf(fmaxf(iou, 1e-7f));
            float s    = __ldg(pred_scores + (size_t)a * C_N + L);
            float cls  = g_total_neg[a] + sp_diff(s);
            float cost = __fadd_rn(__fadd_rn(cls, __fmul_rn(3.0f, iouc)), 1e10f);
            unsigned long long k = packKey(cost, (unsigned)a);
            if (k < best) best = k;
        }
        for (int o = 16; o; o >>= 1) {
            unsigned long long oth = __shfl_down_sync(0xffffffffu, best, o);
            best = (oth < best) ? oth : best;
        }
        if (lane == 0) swmin[wid] = best;
        __syncthreads();
        if (tid == 0) {
            unsigned long long w = swmin[0];
            for (int i = 1; i < NT / 32; i++) if (swmin[i] < w) w = swmin[i];
            atomicMax(&g_assigned[(int)(w & 0xffffffffu)], g);
        }
    }
}

// ---- kernel 3: labels + bboxes + one-hot scatter (scores pre-zeroed) ----
__global__ void finalize_kernel(const float* __restrict__ pred_bboxes,
                                const int*   __restrict__ gt_labels,
                                const float* __restrict__ gt_bboxes,
                                float* __restrict__ out)
{
    int a = blockIdx.x * blockDim.x + threadIdx.x;
    if (a >= A_N) return;

    int  g    = g_assigned[a];
    bool pos  = (g >= 0);
    int  safe = pos ? g : 0;
    int  label = pos ? gt_labels[safe] : C_N;

    float4 gbx = ((const float4*)gt_bboxes)[safe];

    out[a] = (float)label;

    float4* ob = (float4*)(out + A_N);
    ob[a] = pos ? gbx : make_float4(0.f, 0.f, 0.f, 0.f);

    if (pos) {
        float4 pb = ((const float4*)pred_bboxes)[a];
        float w = fmaxf(fminf(pb.z, gbx.z) - fmaxf(pb.x, gbx.x), 0.0f);
        float h = fmaxf(fminf(pb.w, gbx.w) - fmaxf(pb.y, gbx.y), 0.0f);
        float ov = w * h;
        float area_p = (pb.z - pb.x) * (pb.w - pb.y);
        float area_g = (gbx.z - gbx.x) * (gbx.w - gbx.y);
        float iou = ov / (area_p + area_g - ov + 1e-6f);
        out[(size_t)5 * A_N + (size_t)a * (C_N + 1) + label] = iou;
    }
}

extern "C" void kernel_launch(void* const* d_in, const int* in_sizes, int n_in,
                              void* d_out, int out_size) {
    const float* pred_scores   = (const float*)d_in[0];
    const float* pred_bboxes   = (const float*)d_in[1];
    const float* anchor_points = (const float*)d_in[2];
    const int*   gt_labels     = (const int*)  d_in[3];
    const float* gt_bboxes     = (const float*)d_in[4];
    float* out = (float*)d_out;

    prep_kernel<<<PREP_BLOCKS, PREP_NT>>>(pred_scores, out);
    topk_kernel<<<G_N, NT>>>(pred_scores, pred_bboxes, anchor_points,
                             gt_labels, gt_bboxes);
    finalize_kernel<<<(A_N + 255) / 256, 256>>>(pred_bboxes, gt_labels, gt_bboxes, out);
}

// round 15
// speedup vs baseline: 1.3672x; 1.1015x over previous
#include <cuda_runtime.h>
#include <math.h>
#include <float.h>

#define A_N 33600
#define G_N 256
#define C_N 80
#define TOPK 10
#define NT   512
#define CAP  2048        // max inside anchors/GT; 208x208 box -> mean ~887, sigma ~29
#define PREP_NT 256
#define PREP_BLOCKS 2100 // warp w handles score rows 2w, 2w+1
#define BINS 40          // 40x40 grid, 32px bins
#define BINW_INV (1.0f / 32.0f)
#define BCAP 96          // anchors per bin: mean ~21, Poisson, +10 sigma headroom
#define SENT 0xFFFFFFFFFFFFFFFFULL

// Scratch (allocation-free: __device__ globals)
__device__ float g_total_neg[A_N];
__device__ int   g_assigned[A_N];
__device__ int   g_bincnt[BINS * BINS];            // zero at load; re-zeroed by finalize
__device__ int   g_binidx[BINS * BINS * BCAP];

// monotone float -> uint mapping, packed with index: lexicographic (cost asc, idx asc)
__device__ __forceinline__ unsigned long long packKey(float v, unsigned idx) {
    unsigned u = __float_as_uint(v);
    u = (u & 0x80000000u) ? ~u : (u | 0x80000000u);
    return (((unsigned long long)u) << 32) | (unsigned long long)idx;
}

// softplus difference with the reference's rounding sequence
__device__ __forceinline__ float sp_diff(float s) {
    float l = log1pf(expf(-fabsf(s)));
    return (fmaxf(-s, 0.0f) + l) - (fmaxf(s, 0.0f) + l);
}

// fast softplus sum of 4: sum max(x,0) + log(prod(1 + exp(-|x|))), prod in (1,16]
__device__ __forceinline__ float sp4(float4 v) {
    float m = fmaxf(v.x, 0.0f) + fmaxf(v.y, 0.0f) + fmaxf(v.z, 0.0f) + fmaxf(v.w, 0.0f);
    float p = (1.0f + __expf(-fabsf(v.x))) * (1.0f + __expf(-fabsf(v.y)))
            * (1.0f + __expf(-fabsf(v.z))) * (1.0f + __expf(-fabsf(v.w)));
    return m + __logf(p);
}

// ---- kernel 1: prep = total_neg (2 rows/warp) + init + zero scores + binning ----
__global__ __launch_bounds__(PREP_NT) void prep_kernel(
    const float* __restrict__ scores,
    const float* __restrict__ anchor_points,
    float* __restrict__ out)
{
    const int gid = blockIdx.x * PREP_NT + threadIdx.x;

    if (gid < A_N) {
        g_assigned[gid] = -1;
        // spatial binning of anchors (g_bincnt zeroed at load / by prior finalize)
        float2 p = ((const float2*)anchor_points)[gid];
        int bx = min(BINS - 1, (int)(p.x * BINW_INV));
        int by = min(BINS - 1, (int)(p.y * BINW_INV));
        int b = by * BINS + bx;
        int s = atomicAdd(&g_bincnt[b], 1);
        if (s < BCAP) g_binidx[b * BCAP + s] = gid;
    }

    const int n4 = (A_N * (C_N + 1)) / 4;   // 680400 float4s in the scores region
    float4* zp = (float4*)(out + (size_t)5 * A_N);
    for (int i = gid; i < n4; i += PREP_BLOCKS * PREP_NT)
        zp[i] = make_float4(0.f, 0.f, 0.f, 0.f);

    // warp w covers rows r0=2w, r1=2w+1: 40 float4s = 640 contiguous bytes
    const int w = gid >> 5, lane = gid & 31;
    const float4* s4 = (const float4*)scores;
    const size_t B = (size_t)w * 40;

    float4 v = __ldg(s4 + B + lane);            // idx 0..31 (row0: <20, row1: >=20)
    float t = sp4(v);
    float s0 = (lane < 20) ? t : 0.0f;
    float s1 = (lane < 20) ? 0.0f : t;
    if (lane < 8) s1 += sp4(__ldg(s4 + B + 32 + lane));   // idx 32..39 (row1)

#pragma unroll
    for (int o = 16; o; o >>= 1) {
        s0 += __shfl_xor_sync(0xffffffffu, s0, o);
        s1 += __shfl_xor_sync(0xffffffffu, s1, o);
    }
    if (lane == 0)
        *(float2*)(g_total_neg + 2 * w) = make_float2(s0, s1);
}

// ---- kernel 2: per-GT binned scan -> dense cost -> warp top-k -> scatter ----
__global__ __launch_bounds__(NT) void topk_kernel(
    const float* __restrict__ pred_scores,
    const float* __restrict__ pred_bboxes,
    const float* __restrict__ anchor_points,
    const int*   __restrict__ gt_labels,
    const float* __restrict__ gt_bboxes)
{
    const int g   = blockIdx.x;
    const int tid = threadIdx.x;
    const int lane = tid & 31, wid = tid >> 5;

    const float4 gb = ((const float4*)gt_bboxes)[g];
    const float gx1 = gb.x, gy1 = gb.y, gx2 = gb.z, gy2 = gb.w;
    const int   L   = gt_labels[g];
    const float area_g = (gx2 - gx1) * (gy2 - gy1);

    const float2* ap2 = (const float2*)anchor_points;
    const float4* pb4 = (const float4*)pred_bboxes;

    __shared__ int s_list[CAP];
    __shared__ unsigned long long s_keys[CAP];
    __shared__ unsigned long long swmin[NT / 32];
    __shared__ int s_n;
    __shared__ int s_cnt;

    if (tid == 0) { s_n = 0; s_cnt = 0; }
    __syncthreads();

    // ---- phase 1: binned inside scan (bin() monotone, same expr as prep) ----
    {
        int bx0 = max(0, (int)(gx1 * BINW_INV));
        int bx1 = min(BINS - 1, (int)(gx2 * BINW_INV));
        int by0 = max(0, (int)(gy1 * BINW_INV));
        int by1 = min(BINS - 1, (int)(gy2 * BINW_INV));
        if (bx1 >= bx0 && by1 >= by0) {
            const int nbx = bx1 - bx0 + 1;
            const int total = nbx * (by1 - by0 + 1) * BCAP;
            for (int i = tid; i < total; i += NT) {
                int b    = i / BCAP;
                int slot = i - b * BCAP;
                int bx = bx0 + (b % nbx);
                int by = by0 + (b / nbx);
                int bin = by * BINS + bx;
                if (slot < g_bincnt[bin]) {
                    int a = g_binidx[bin * BCAP + slot];
                    float2 p = __ldg(ap2 + a);
                    if (p.x >= gx1 && p.x <= gx2 && p.y >= gy1 && p.y <= gy2) {
                        int s = atomicAdd(&s_n, 1);
                        if (s < CAP) s_list[s] = a;
                    }
                }
            }
        }
    }
    __syncthreads();
    const int n = min(s_n, CAP);

    if (n > 0) {
        // ---- phase 2: dense cost over compacted candidates (mask = 0 inside) ----
        int cnt = 0;
        for (int i = tid; i < n; i += NT) {
            int a = s_list[i];
            float4 pb = __ldg(pb4 + a);
            float w  = fmaxf(fminf(pb.z, gx2) - fmaxf(pb.x, gx1), 0.0f);
            float h  = fmaxf(fminf(pb.w, gy2) - fmaxf(pb.y, gy1), 0.0f);
            float ov = w * h;
            cnt += (ov > 0.0f);
            float area_p = (pb.z - pb.x) * (pb.w - pb.y);
            float iou  = ov / (area_p + area_g - ov + 1e-6f);
            float iouc = -logf(fmaxf(iou, 1e-7f));
            float s    = __ldg(pred_scores + (size_t)a * C_N + L);
            float cls  = g_total_neg[a] + sp_diff(s);
            float cost = __fadd_rn(cls, __fmul_rn(3.0f, iouc));
            s_keys[i] = packKey(cost, (unsigned)a);
        }
        for (int o = 16; o; o >>= 1) cnt += __shfl_down_sync(0xffffffffu, cnt, o);
        if (lane == 0 && cnt > 0) atomicAdd(&s_cnt, cnt);
        __syncthreads();

        // ---- phase 3: single-warp exact top-dyn_k selection + scatter ----
        if (wid == 0) {
            int c = s_cnt;
            int k = (c < 1) ? 1 : ((c > TOPK) ? TOPK : c);
            // dyn_k <= cnt <= n, and every inside cost < every outside cost,
            // so the global top-dyn_k are exactly among these candidates.
            unsigned long long loc[TOPK];
#pragma unroll
            for (int j = 0; j < TOPK; j++) loc[j] = SENT;
            for (int i = lane; i < n; i += 32) {
                unsigned long long v = s_keys[i];
                if (v < loc[TOPK - 1]) {
                    loc[TOPK - 1] = v;
#pragma unroll
                    for (int j = TOPK - 1; j > 0; j--) {
                        bool sw = loc[j] < loc[j - 1];
                        unsigned long long lo = sw ? loc[j] : loc[j - 1];
                        unsigned long long hi = sw ? loc[j - 1] : loc[j];
                        loc[j - 1] = lo; loc[j] = hi;
                    }
                }
            }
            int p = 0;
            for (int r = 0; r < k; r++) {
                unsigned long long cand = (p < TOPK) ? loc[p] : SENT;
                unsigned long long m = cand;
#pragma unroll
                for (int o = 16; o; o >>= 1) {
                    unsigned long long oth = __shfl_xor_sync(0xffffffffu, m, o);
                    m = (oth < m) ? oth : m;
                }
                if (lane == 0) atomicMax(&g_assigned[(int)(m & 0xffffffffu)], g);
                if (cand == m) p++;
            }
        }
    } else {
        // ---- zero inside anchors: dyn_k = 1, global argmin (all outside) ----
        unsigned long long best = SENT;
        for (int a = tid; a < A_N; a += NT) {
            float4 pb = __ldg(pb4 + a);
            float w  = fmaxf(fminf(pb.z, gx2) - fmaxf(pb.x, gx1), 0.0f);
            float h  = fmaxf(fminf(pb.w, gy2) - fmaxf(pb.y, gy1), 0.0f);
            float ov = w * h;
            float area_p = (pb.z - pb.x) * (pb.w - pb.y);
            float iou  = ov / (area_p + area_g - ov + 1e-6f);
            float iouc = -logf(fmaxf(iou, 1e-7f));
            float s    = __ldg(pred_scores + (size_t)a * C_N + L);
            float cls  = g_total_neg[a] + sp_diff(s);
            float cost = __fadd_rn(__fadd_rn(cls, __fmul_rn(3.0f, iouc)), 1e10f);
            unsigned long long k = packKey(cost, (unsigned)a);
            if (k < best) best = k;
        }
        for (int o = 16; o; o >>= 1) {
            unsigned long long oth = __shfl_down_sync(0xffffffffu, best, o);
            best = (oth < best) ? oth : best;
        }
        if (lane == 0) swmin[wid] = best;
        __syncthreads();
        if (tid == 0) {
            unsigned long long w = swmin[0];
            for (int i = 1; i < NT / 32; i++) if (swmin[i] < w) w = swmin[i];
            atomicMax(&g_assigned[(int)(w & 0xffffffffu)], g);
        }
    }
}

// ---- kernel 3: labels + bboxes + one-hot scatter + bincnt re-zero ----
__global__ void finalize_kernel(const float* __restrict__ pred_bboxes,
                                const int*   __restrict__ gt_labels,
                                const float* __restrict__ gt_bboxes,
                                float* __restrict__ out)
{
    int a = blockIdx.x * blockDim.x + threadIdx.x;
    if (a >= A_N) return;

    if (a < BINS * BINS) g_bincnt[a] = 0;   // ready for the next replay

    int  g    = g_assigned[a];
    bool pos  = (g >= 0);
    int  safe = pos ? g : 0;
    int  label = pos ? gt_labels[safe] : C_N;

    float4 gbx = ((const float4*)gt_bboxes)[safe];

    out[a] = (float)label;

    float4* ob = (float4*)(out + A_N);
    ob[a] = pos ? gbx : make_float4(0.f, 0.f, 0.f, 0.f);

    if (pos) {
        float4 pb = ((const float4*)pred_bboxes)[a];
        float w = fmaxf(fminf(pb.z, gbx.z) - fmaxf(pb.x, gbx.x), 0.0f);
        float h = fmaxf(fminf(pb.w, gbx.w) - fmaxf(pb.y, gbx.y), 0.0f);
        float ov = w * h;
        float area_p = (pb.z - pb.x) * (pb.w - pb.y);
        float area_g = (gbx.z - gbx.x) * (gbx.w - gbx.y);
        float iou = ov / (area_p + area_g - ov + 1e-6f);
        out[(size_t)5 * A_N + (size_t)a * (C_N + 1) + label] = iou;
    }
}

extern "C" void kernel_launch(void* const* d_in, const int* in_sizes, int n_in,
                              void* d_out, int out_size) {
    const float* pred_scores   = (const float*)d_in[0];
    const float* pred_bboxes   = (const float*)d_in[1];
    const float* anchor_points = (const float*)d_in[2];
    const int*   gt_labels     = (const int*)  d_in[3];
    const float* gt_bboxes     = (const float*)d_in[4];
    float* out = (float*)d_out;

    prep_kernel<<<PREP_BLOCKS, PREP_NT>>>(pred_scores, anchor_points, out);
    topk_kernel<<<G_N, NT>>>(pred_scores, pred_bboxes, anchor_points,
                             gt_labels, gt_bboxes);
    finalize_kernel<<<(A_N + 255) / 256, 256>>>(pred_bboxes, gt_labels, gt_bboxes, out);
}